// round 1
// baseline (speedup 1.0000x reference)
#include <cuda_runtime.h>
#include <math.h>

#define BB 16
#define FF 2048
#define NSP 64
#define ROWS (BB*FF)      // 32768
#define KTOP 1024

// Scratch (device globals; no allocation in kernel_launch)
__device__ float g_A[BB*FF*128];                 // [b][f][0:64]=Xn, [64:128]=Mn  (16 MB)
__device__ float g_YX[67108864];                 // [b][f][g]  (256 MB)
__device__ float g_stats[BB*4*NSP];              // per b: meanX[64], invX[64], meanM[64], invM[64]
__device__ float g_C[ROWS];

// ---------------------------------------------------------------------------
// Kernel 1: per-(b,n) sum and sumsq over F for X and M
// ---------------------------------------------------------------------------
__global__ void __launch_bounds__(1024) stats_kernel(const float* __restrict__ X,
                                                     const float* __restrict__ Mm) {
    int b = blockIdx.x;
    int tid = threadIdx.x;
    int n4 = tid & 15;          // float4 group over 64 spatial cols
    int chunk = tid >> 4;       // 0..63, each 32 f-rows

    const float4* X4 = (const float4*)X + (size_t)b * FF * 16;
    const float4* M4 = (const float4*)Mm + (size_t)b * FF * 16;

    float4 sx = {0,0,0,0}, sxx = {0,0,0,0}, sm = {0,0,0,0}, smm = {0,0,0,0};
    int f0 = chunk * 32;
    for (int r = 0; r < 32; r++) {
        float4 xv = X4[(size_t)(f0 + r) * 16 + n4];
        sx.x += xv.x; sx.y += xv.y; sx.z += xv.z; sx.w += xv.w;
        sxx.x += xv.x*xv.x; sxx.y += xv.y*xv.y; sxx.z += xv.z*xv.z; sxx.w += xv.w*xv.w;
        float4 mv = M4[(size_t)(f0 + r) * 16 + n4];
        sm.x += mv.x; sm.y += mv.y; sm.z += mv.z; sm.w += mv.w;
        smm.x += mv.x*mv.x; smm.y += mv.y*mv.y; smm.z += mv.z*mv.z; smm.w += mv.w*mv.w;
    }

    __shared__ float4 red[64][16];
    __shared__ float sum1[64], sum2[64], sum3[64], sum4[64];

    // 4 reduction rounds reusing 'red'
    red[chunk][n4] = sx; __syncthreads();
    if (tid < 64) {
        float s = 0;
        for (int c = 0; c < 64; c++) {
            float4 q = red[c][tid >> 2];
            float v = (tid & 2) ? ((tid & 1) ? q.w : q.z) : ((tid & 1) ? q.y : q.x);
            s += v;
        }
        sum1[tid] = s;
    }
    __syncthreads();
    red[chunk][n4] = sxx; __syncthreads();
    if (tid < 64) {
        float s = 0;
        for (int c = 0; c < 64; c++) {
            float4 q = red[c][tid >> 2];
            float v = (tid & 2) ? ((tid & 1) ? q.w : q.z) : ((tid & 1) ? q.y : q.x);
            s += v;
        }
        sum2[tid] = s;
    }
    __syncthreads();
    red[chunk][n4] = sm; __syncthreads();
    if (tid < 64) {
        float s = 0;
        for (int c = 0; c < 64; c++) {
            float4 q = red[c][tid >> 2];
            float v = (tid & 2) ? ((tid & 1) ? q.w : q.z) : ((tid & 1) ? q.y : q.x);
            s += v;
        }
        sum3[tid] = s;
    }
    __syncthreads();
    red[chunk][n4] = smm; __syncthreads();
    if (tid < 64) {
        float s = 0;
        for (int c = 0; c < 64; c++) {
            float4 q = red[c][tid >> 2];
            float v = (tid & 2) ? ((tid & 1) ? q.w : q.z) : ((tid & 1) ? q.y : q.x);
            s += v;
        }
        sum4[tid] = s;

        float meanX = sum1[tid] * (1.0f / FF);
        float invX  = 1.0f / (sqrtf(fmaxf(sum2[tid] - (float)FF * meanX * meanX, 0.0f)) + 1e-10f);
        float meanM = sum3[tid] * (1.0f / FF);
        float invM  = 1.0f / (sqrtf(fmaxf(sum4[tid] - (float)FF * meanM * meanM, 0.0f)) + 1e-10f);
        g_stats[b*256 + tid]       = meanX;
        g_stats[b*256 + 64 + tid]  = invX;
        g_stats[b*256 + 128 + tid] = meanM;
        g_stats[b*256 + 192 + tid] = invM;
    }
}

// ---------------------------------------------------------------------------
// Kernel 2: write A[b][f][c] = normalized [Xn | Mn]
// ---------------------------------------------------------------------------
__global__ void __launch_bounds__(256) norm_kernel(const float* __restrict__ X,
                                                   const float* __restrict__ Mm) {
    int b = blockIdx.y;
    int fbase = blockIdx.x * 128;
    int tid = threadIdx.x;

    __shared__ float s_mean[128], s_inv[128];
    if (tid < 64) {
        s_mean[tid] = g_stats[b*256 + tid];
        s_inv[tid]  = g_stats[b*256 + 64 + tid];
    } else if (tid < 128) {
        s_mean[tid] = g_stats[b*256 + 64 + tid];   // 128 + (tid-64)
        s_inv[tid]  = g_stats[b*256 + 128 + tid];  // 192 + (tid-64)
    }
    __syncthreads();

    int c = tid & 127;
    int rh = tid >> 7;
    const float* src = (c < 64) ? (X + (size_t)b * FF * 64 + c)
                                : (Mm + (size_t)b * FF * 64 + (c - 64));
    float mean = s_mean[c], inv = s_inv[c];
    for (int r = 0; r < 64; r++) {
        int f = fbase + r * 2 + rh;
        float v = src[(size_t)f * 64];
        g_A[((size_t)b * FF + f) * 128 + c] = (v - mean) * inv;
    }
}

// ---------------------------------------------------------------------------
// Kernel 3: per-batch YX = A @ B^T where B cols = A cols rotated by 64 (K=128)
// 128x128 tile per block, 256 threads, 8x8 microtile
// ---------------------------------------------------------------------------
__global__ void __launch_bounds__(256) gemm_kernel() {
    int b  = blockIdx.z;
    int mt = blockIdx.y * 128;
    int nt = blockIdx.x * 128;
    int tid = threadIdx.x;
    int tx = tid & 15, ty = tid >> 4;

    __shared__ float As[32][132];
    __shared__ float Bs[32][132];

    const float* Abase = g_A + ((size_t)b * FF + mt) * 128;
    const float* Bbase = g_A + ((size_t)b * FF + nt) * 128;

    float acc[8][8];
    #pragma unroll
    for (int i = 0; i < 8; i++)
        #pragma unroll
        for (int j = 0; j < 8; j++) acc[i][j] = 0.0f;

    for (int kc = 0; kc < 4; kc++) {
        int aoff = kc * 32;
        int boff = (aoff + 64) & 127;
        #pragma unroll
        for (int l = 0; l < 4; l++) {
            int idx = tid + l * 256;
            int row = idx >> 3;
            int kg = (idx & 7) * 4;
            float4 va = *(const float4*)(Abase + (size_t)row * 128 + aoff + kg);
            As[kg+0][row] = va.x; As[kg+1][row] = va.y;
            As[kg+2][row] = va.z; As[kg+3][row] = va.w;
            float4 vb = *(const float4*)(Bbase + (size_t)row * 128 + boff + kg);
            Bs[kg+0][row] = vb.x; Bs[kg+1][row] = vb.y;
            Bs[kg+2][row] = vb.z; Bs[kg+3][row] = vb.w;
        }
        __syncthreads();
        #pragma unroll
        for (int kk = 0; kk < 32; kk++) {
            float4 a0 = *(const float4*)&As[kk][ty*8];
            float4 a1 = *(const float4*)&As[kk][ty*8+4];
            float4 b0 = *(const float4*)&Bs[kk][tx*8];
            float4 b1 = *(const float4*)&Bs[kk][tx*8+4];
            float av[8] = {a0.x,a0.y,a0.z,a0.w,a1.x,a1.y,a1.z,a1.w};
            float bv[8] = {b0.x,b0.y,b0.z,b0.w,b1.x,b1.y,b1.z,b1.w};
            #pragma unroll
            for (int i = 0; i < 8; i++)
                #pragma unroll
                for (int j = 0; j < 8; j++)
                    acc[i][j] += av[i] * bv[j];
        }
        __syncthreads();
    }

    float* out = g_YX + ((size_t)b * FF + mt + ty * 8) * FF + nt + tx * 8;
    #pragma unroll
    for (int i = 0; i < 8; i++) {
        float4 w0 = {acc[i][0], acc[i][1], acc[i][2], acc[i][3]};
        float4 w1 = {acc[i][4], acc[i][5], acc[i][6], acc[i][7]};
        *(float4*)(out + (size_t)i * FF)     = w0;
        *(float4*)(out + (size_t)i * FF + 4) = w1;
    }
}

// ---------------------------------------------------------------------------
// Kernel 4: per-row radix-select top-1024 + exp sums -> C[row]
// ---------------------------------------------------------------------------
__device__ __forceinline__ float untr(unsigned uu) {
    unsigned bts = uu ^ ((uu & 0x80000000u) ? 0x80000000u : 0xFFFFFFFFu);
    return __uint_as_float(bts);
}

__global__ void __launch_bounds__(256) topk_kernel() {
    int row = blockIdx.x;
    int f = row & (FF - 1);
    const float* yr = g_YX + (size_t)row * FF;
    int tid = threadIdx.x;

    __shared__ unsigned u[FF];
    __shared__ unsigned hist[256];
    __shared__ unsigned scan[256];
    __shared__ unsigned sh_prefix, sh_rem, sh_umax;
    __shared__ unsigned wmax[8];
    __shared__ float wse[8], wsed[8];
    __shared__ int eqCount;
    __shared__ int eqIdx[256];

    if (tid == 0) { sh_prefix = 0; sh_rem = KTOP; eqCount = 0; }

    unsigned um = 0;
    for (int i = tid; i < FF; i += 256) {
        unsigned bts = __float_as_uint(yr[i]);
        unsigned uu = bts ^ ((unsigned)((int)bts >> 31) | 0x80000000u);
        u[i] = uu;
        um = max(um, uu);
    }
    um = __reduce_max_sync(0xffffffffu, um);
    if ((tid & 31) == 0) wmax[tid >> 5] = um;
    __syncthreads();
    if (tid == 0) {
        unsigned m2 = 0;
        for (int w = 0; w < 8; w++) m2 = max(m2, wmax[w]);
        sh_umax = m2;
    }
    __syncthreads();
    float vmax = untr(sh_umax);

    for (int pass = 0; pass < 4; pass++) {
        int shift = 24 - pass * 8;
        hist[tid] = 0;
        __syncthreads();
        unsigned prefix = sh_prefix;
        unsigned mask = pass ? (0xFFFFFFFFu << (shift + 8)) : 0u;
        for (int i = tid; i < FF; i += 256) {
            unsigned uu = u[i];
            if ((uu & mask) == prefix)
                atomicAdd(&hist[(uu >> shift) & 255], 1u);
        }
        __syncthreads();
        scan[tid] = hist[tid];
        __syncthreads();
        for (int off = 1; off < 256; off <<= 1) {
            unsigned t2 = (tid + off < 256) ? scan[tid + off] : 0u;
            __syncthreads();
            scan[tid] += t2;
            __syncthreads();
        }
        unsigned rem = sh_rem;
        __syncthreads();
        unsigned hi = (tid == 255) ? 0u : scan[tid + 1];
        if (scan[tid] >= rem && hi < rem) {
            sh_prefix = prefix | ((unsigned)tid << shift);
            sh_rem = rem - hi;
        }
        __syncthreads();
    }

    unsigned T = sh_prefix;
    int need = (int)sh_rem;

    float se = 0.0f, sed = 0.0f;
    for (int i = tid; i < FF; i += 256) {
        unsigned uu = u[i];
        if (uu > T) {
            float v = untr(uu);
            float e = __expf(v - vmax);
            se += e;
            sed += e * (float)abs(i - f);
        } else if (uu == T) {
            int p = atomicAdd(&eqCount, 1);
            if (p < 256) eqIdx[p] = i;
        }
    }
    #pragma unroll
    for (int o = 16; o; o >>= 1) {
        se  += __shfl_down_sync(0xffffffffu, se, o);
        sed += __shfl_down_sync(0xffffffffu, sed, o);
    }
    if ((tid & 31) == 0) { wse[tid >> 5] = se; wsed[tid >> 5] = sed; }
    __syncthreads();
    if (tid == 0) {
        float SE = 0, SED = 0;
        for (int w = 0; w < 8; w++) { SE += wse[w]; SED += wsed[w]; }
        int ec = eqCount; if (ec > 256) ec = 256;
        float eT = __expf(untr(T) - vmax);
        int take = need < ec ? need : ec;
        if (ec > need) {
            // need smallest `need` indices (jax tie-break: lower index first)
            for (int a = 1; a < ec; a++) {
                int key = eqIdx[a]; int bnd = a - 1;
                while (bnd >= 0 && eqIdx[bnd] > key) { eqIdx[bnd+1] = eqIdx[bnd]; bnd--; }
                eqIdx[bnd+1] = key;
            }
        }
        int sumd = 0;
        for (int j = 0; j < take; j++) sumd += abs(eqIdx[j] - f);
        SE  += (float)take * eT;
        SED += eT * (float)sumd;
        g_C[row] = SED / ((float)KTOP * SE);
    }
}

// ---------------------------------------------------------------------------
// Kernel 5: out = mean( exp(-C + min(C) - 1e-6) )
// ---------------------------------------------------------------------------
__global__ void __launch_bounds__(1024) final_kernel(float* __restrict__ out) {
    int tid = threadIdx.x;
    __shared__ float wred[32];
    __shared__ float s_min;

    float mn = 3.4e38f;
    for (int i = tid; i < ROWS; i += 1024) mn = fminf(mn, g_C[i]);
    #pragma unroll
    for (int o = 16; o; o >>= 1) mn = fminf(mn, __shfl_down_sync(0xffffffffu, mn, o));
    if ((tid & 31) == 0) wred[tid >> 5] = mn;
    __syncthreads();
    if (tid == 0) {
        float m2 = wred[0];
        for (int w = 1; w < 32; w++) m2 = fminf(m2, wred[w]);
        s_min = m2;
    }
    __syncthreads();
    float cmin = s_min;

    float s = 0.0f;
    for (int i = tid; i < ROWS; i += 1024) s += expf(-g_C[i] + cmin - 1e-6f);
    #pragma unroll
    for (int o = 16; o; o >>= 1) s += __shfl_down_sync(0xffffffffu, s, o);
    __syncthreads();  // wred reuse
    if ((tid & 31) == 0) wred[tid >> 5] = s;
    __syncthreads();
    if (tid == 0) {
        float S = 0;
        for (int w = 0; w < 32; w++) S += wred[w];
        out[0] = S / (float)ROWS;
    }
}

extern "C" void kernel_launch(void* const* d_in, const int* in_sizes, int n_in,
                              void* d_out, int out_size) {
    const float* X  = (const float*)d_in[0];
    const float* Mm = (const float*)d_in[1];
    float* out = (float*)d_out;

    stats_kernel<<<BB, 1024>>>(X, Mm);
    norm_kernel<<<dim3(16, BB), 256>>>(X, Mm);
    gemm_kernel<<<dim3(16, 16, BB), 256>>>();
    topk_kernel<<<ROWS, 256>>>();
    final_kernel<<<1, 1024>>>(out);
}

// round 4
// speedup vs baseline: 1.3252x; 1.3252x over previous
#include <cuda_runtime.h>
#include <math.h>

#define BB 16
#define FF 2048
#define NSP 64
#define ROWS (BB*FF)      // 32768
#define KTOP 1024

// Scratch (device globals; no allocation in kernel_launch)
__device__ float g_A[BB*FF*128];                 // [b][f][0:64]=Xn, [64:128]=Mn  (16 MB)
__device__ float g_YX[67108864];                 // [b][f][g]  (256 MB)
__device__ float g_stats[BB*4*NSP];
__device__ float g_C[ROWS];

// ---------------------------------------------------------------------------
// Kernel 1: per-(b,n) sum and sumsq over F for X and M
// ---------------------------------------------------------------------------
__global__ void __launch_bounds__(1024) stats_kernel(const float* __restrict__ X,
                                                     const float* __restrict__ Mm) {
    int b = blockIdx.x;
    int tid = threadIdx.x;
    int n4 = tid & 15;
    int chunk = tid >> 4;

    const float4* X4 = (const float4*)X + (size_t)b * FF * 16;
    const float4* M4 = (const float4*)Mm + (size_t)b * FF * 16;

    float4 sx = {0,0,0,0}, sxx = {0,0,0,0}, sm = {0,0,0,0}, smm = {0,0,0,0};
    int f0 = chunk * 32;
    for (int r = 0; r < 32; r++) {
        float4 xv = X4[(size_t)(f0 + r) * 16 + n4];
        sx.x += xv.x; sx.y += xv.y; sx.z += xv.z; sx.w += xv.w;
        sxx.x += xv.x*xv.x; sxx.y += xv.y*xv.y; sxx.z += xv.z*xv.z; sxx.w += xv.w*xv.w;
        float4 mv = M4[(size_t)(f0 + r) * 16 + n4];
        sm.x += mv.x; sm.y += mv.y; sm.z += mv.z; sm.w += mv.w;
        smm.x += mv.x*mv.x; smm.y += mv.y*mv.y; smm.z += mv.z*mv.z; smm.w += mv.w*mv.w;
    }

    __shared__ float4 red[64][16];
    __shared__ float sum1[64], sum2[64], sum3[64], sum4[64];

    red[chunk][n4] = sx; __syncthreads();
    if (tid < 64) {
        float s = 0;
        for (int c = 0; c < 64; c++) {
            float4 q = red[c][tid >> 2];
            float v = (tid & 2) ? ((tid & 1) ? q.w : q.z) : ((tid & 1) ? q.y : q.x);
            s += v;
        }
        sum1[tid] = s;
    }
    __syncthreads();
    red[chunk][n4] = sxx; __syncthreads();
    if (tid < 64) {
        float s = 0;
        for (int c = 0; c < 64; c++) {
            float4 q = red[c][tid >> 2];
            float v = (tid & 2) ? ((tid & 1) ? q.w : q.z) : ((tid & 1) ? q.y : q.x);
            s += v;
        }
        sum2[tid] = s;
    }
    __syncthreads();
    red[chunk][n4] = sm; __syncthreads();
    if (tid < 64) {
        float s = 0;
        for (int c = 0; c < 64; c++) {
            float4 q = red[c][tid >> 2];
            float v = (tid & 2) ? ((tid & 1) ? q.w : q.z) : ((tid & 1) ? q.y : q.x);
            s += v;
        }
        sum3[tid] = s;
    }
    __syncthreads();
    red[chunk][n4] = smm; __syncthreads();
    if (tid < 64) {
        float s = 0;
        for (int c = 0; c < 64; c++) {
            float4 q = red[c][tid >> 2];
            float v = (tid & 2) ? ((tid & 1) ? q.w : q.z) : ((tid & 1) ? q.y : q.x);
            s += v;
        }
        sum4[tid] = s;

        float meanX = sum1[tid] * (1.0f / FF);
        float invX  = 1.0f / (sqrtf(fmaxf(sum2[tid] - (float)FF * meanX * meanX, 0.0f)) + 1e-10f);
        float meanM = sum3[tid] * (1.0f / FF);
        float invM  = 1.0f / (sqrtf(fmaxf(sum4[tid] - (float)FF * meanM * meanM, 0.0f)) + 1e-10f);
        g_stats[b*256 + tid]       = meanX;
        g_stats[b*256 + 64 + tid]  = invX;
        g_stats[b*256 + 128 + tid] = meanM;
        g_stats[b*256 + 192 + tid] = invM;
    }
}

// ---------------------------------------------------------------------------
// Kernel 2: write A[b][f][c] = normalized [Xn | Mn]
// ---------------------------------------------------------------------------
__global__ void __launch_bounds__(256) norm_kernel(const float* __restrict__ X,
                                                   const float* __restrict__ Mm) {
    int b = blockIdx.y;
    int fbase = blockIdx.x * 128;
    int tid = threadIdx.x;

    __shared__ float s_mean[128], s_inv[128];
    if (tid < 64) {
        s_mean[tid] = g_stats[b*256 + tid];
        s_inv[tid]  = g_stats[b*256 + 64 + tid];
    } else if (tid < 128) {
        s_mean[tid] = g_stats[b*256 + 64 + tid];
        s_inv[tid]  = g_stats[b*256 + 128 + tid];
    }
    __syncthreads();

    int c = tid & 127;
    int rh = tid >> 7;
    const float* src = (c < 64) ? (X + (size_t)b * FF * 64 + c)
                                : (Mm + (size_t)b * FF * 64 + (c - 64));
    float mean = s_mean[c], inv = s_inv[c];
    for (int r = 0; r < 64; r++) {
        int f = fbase + r * 2 + rh;
        float v = src[(size_t)f * 64];
        g_A[((size_t)b * FF + f) * 128 + c] = (v - mean) * inv;
    }
}

// ---------------------------------------------------------------------------
// Kernel 3: symmetric GEMM. YX = A @ B^T (B cols = A cols rotated by 64).
// Only upper-triangular tiles computed; off-diagonal tiles written twice
// (direct + transposed). Inner loop uses packed fma.rn.f32x2.
// ---------------------------------------------------------------------------
#define FFMA2(d, a, bb) asm("fma.rn.f32x2 %0, %1, %2, %0;" : "+l"(d) : "l"(a), "l"(bb))

__device__ __forceinline__ unsigned long long packdup(float x) {
    unsigned long long d;
    asm("mov.b64 %0, {%1, %1};" : "=l"(d) : "f"(x));
    return d;
}
__device__ __forceinline__ float2 unpk(unsigned long long d) {
    float2 r; asm("mov.b64 {%0, %1}, %2;" : "=f"(r.x), "=f"(r.y) : "l"(d));
    return r;
}

__global__ void __launch_bounds__(256, 2) gemm_kernel() {
    int b = blockIdx.z;
    int t = blockIdx.x;            // 0..135 triangular index
    int rr = 0;
    while (t >= 16 - rr) { t -= 16 - rr; rr++; }
    const int mt = rr * 128;
    const int nt = (rr + t) * 128;

    int tid = threadIdx.x;
    int tx = tid & 15, ty = tid >> 4;

    __shared__ __align__(16) float As[32][132];
    __shared__ __align__(16) float Bs[32][132];

    const float* Abase = g_A + ((size_t)b * FF + mt) * 128;
    const float* Bbase = g_A + ((size_t)b * FF + nt) * 128;

    unsigned long long acc2[8][4];
    #pragma unroll
    for (int i = 0; i < 8; i++)
        #pragma unroll
        for (int j = 0; j < 4; j++) acc2[i][j] = 0ULL;

    const int lrow = tid >> 3;            // 0..31
    const int kg = (tid & 7) * 4;         // 0,4,...,28
    const int vkg = ((kg >> 2) & 7) << 2; // store-side swizzle

    for (int kc = 0; kc < 4; kc++) {
        int aoff = kc * 32;
        int boff = (aoff + 64) & 127;
        #pragma unroll
        for (int l = 0; l < 4; l++) {
            int rowi = lrow + l * 32;
            float4 va = *(const float4*)(Abase + (size_t)rowi * 128 + aoff + kg);
            float4 vb = *(const float4*)(Bbase + (size_t)rowi * 128 + boff + kg);
            int pr = rowi ^ vkg;
            As[kg+0][pr] = va.x; As[kg+1][pr] = va.y;
            As[kg+2][pr] = va.z; As[kg+3][pr] = va.w;
            Bs[kg+0][pr] = vb.x; Bs[kg+1][pr] = vb.y;
            Bs[kg+2][pr] = vb.z; Bs[kg+3][pr] = vb.w;
        }
        __syncthreads();
        #pragma unroll
        for (int kk = 0; kk < 32; kk++) {
            int vv = ((kk >> 2) & 7) << 2;
            const float4 a0 = *(const float4*)&As[kk][(ty*8) ^ vv];
            const float4 a1 = *(const float4*)&As[kk][(ty*8+4) ^ vv];
            const ulonglong2 b0 = *(const ulonglong2*)&Bs[kk][(tx*4) ^ vv];
            const ulonglong2 b1 = *(const ulonglong2*)&Bs[kk][(64+tx*4) ^ vv];
            float av[8] = {a0.x,a0.y,a0.z,a0.w,a1.x,a1.y,a1.z,a1.w};
            #pragma unroll
            for (int i = 0; i < 8; i++) {
                unsigned long long aa = packdup(av[i]);
                FFMA2(acc2[i][0], aa, b0.x);
                FFMA2(acc2[i][1], aa, b0.y);
                FFMA2(acc2[i][2], aa, b1.x);
                FFMA2(acc2[i][3], aa, b1.y);
            }
        }
        __syncthreads();
    }

    float vals[8][8];
    #pragma unroll
    for (int i = 0; i < 8; i++)
        #pragma unroll
        for (int j = 0; j < 4; j++) {
            float2 p = unpk(acc2[i][j]);
            vals[i][j*2]   = p.x;
            vals[i][j*2+1] = p.y;
        }

    // direct write: rows mt+ty*8+i, cols nt+tx*4 (+64)
    {
        float* outp = g_YX + ((size_t)b * FF + mt + ty*8) * FF + nt + tx*4;
        #pragma unroll
        for (int i = 0; i < 8; i++) {
            float4 w0 = {vals[i][0], vals[i][1], vals[i][2], vals[i][3]};
            float4 w1 = {vals[i][4], vals[i][5], vals[i][6], vals[i][7]};
            *(float4*)(outp + (size_t)i * FF)      = w0;
            *(float4*)(outp + (size_t)i * FF + 64) = w1;
        }
    }

    // transposed write for off-diagonal tiles: rows nt+col, cols mt+ty*8..
    if (mt != nt) {
        float* outt = g_YX + ((size_t)b * FF + nt) * FF + mt + ty*8;
        #pragma unroll
        for (int j = 0; j < 8; j++) {
            int col = (j < 4) ? (tx*4 + j) : (64 + tx*4 + (j - 4));
            float4 lo = {vals[0][j], vals[1][j], vals[2][j], vals[3][j]};
            float4 hi = {vals[4][j], vals[5][j], vals[6][j], vals[7][j]};
            *(float4*)(outt + (size_t)col * FF)     = lo;
            *(float4*)(outt + (size_t)col * FF + 4) = hi;
        }
    }
}

// ---------------------------------------------------------------------------
// Kernel 4: per-row radix-select top-1024 + exp sums -> C[row]
// Values in registers; per-warp match-aggregated histograms (no atomics);
// warp-shuffle suffix scan.
// ---------------------------------------------------------------------------
__device__ __forceinline__ float untr(unsigned uu) {
    unsigned bts = uu ^ ((uu & 0x80000000u) ? 0x80000000u : 0xFFFFFFFFu);
    return __uint_as_float(bts);
}

__global__ void __launch_bounds__(256) topk_kernel() {
    int row = blockIdx.x;
    int f = row & (FF - 1);
    const float4* yr = (const float4*)(g_YX + (size_t)row * FF);
    int tid = threadIdx.x;
    int lane = tid & 31, wid = tid >> 5;

    __shared__ unsigned whist[8][257];
    __shared__ unsigned S[256];
    __shared__ unsigned warpTot[8];
    __shared__ unsigned sh_prefix, sh_rem, sh_umax;
    __shared__ unsigned wmax[8];
    __shared__ float wse[8], wsed[8];
    __shared__ int eqCount;
    __shared__ int eqIdx[256];

    if (tid == 0) { sh_prefix = 0; sh_rem = KTOP; eqCount = 0; }

    float4 v0 = yr[tid*2], v1 = yr[tid*2 + 1];
    float fv[8] = {v0.x,v0.y,v0.z,v0.w,v1.x,v1.y,v1.z,v1.w};
    unsigned ur[8];
    unsigned um = 0;
    #pragma unroll
    for (int j = 0; j < 8; j++) {
        unsigned bts = __float_as_uint(fv[j]);
        unsigned uu = bts ^ ((unsigned)((int)bts >> 31) | 0x80000000u);
        ur[j] = uu;
        um = max(um, uu);
    }
    um = __reduce_max_sync(0xffffffffu, um);
    if (lane == 0) wmax[wid] = um;
    __syncthreads();
    if (tid == 0) {
        unsigned m2 = 0;
        for (int w = 0; w < 8; w++) m2 = max(m2, wmax[w]);
        sh_umax = m2;
    }
    __syncthreads();
    float vmax = untr(sh_umax);

    #pragma unroll 1
    for (int pass = 0; pass < 4; pass++) {
        int shift = 24 - pass * 8;
        unsigned prefix = sh_prefix;
        unsigned rem = sh_rem;
        unsigned pmask = pass ? (0xFFFFFFFFu << (shift + 8)) : 0u;

        #pragma unroll
        for (int w = 0; w < 8; w++) whist[w][tid] = 0;
        __syncthreads();

        #pragma unroll
        for (int j = 0; j < 8; j++) {
            unsigned uu = ur[j];
            bool p = (uu & pmask) == prefix;
            unsigned bkt = p ? ((uu >> shift) & 255u) : 0xFFFFFFFFu;
            unsigned mm = __match_any_sync(0xffffffffu, bkt);
            if (p && lane == (__ffs(mm) - 1))
                whist[wid][bkt] += __popc(mm);
        }
        __syncthreads();

        unsigned v = 0;
        #pragma unroll
        for (int w = 0; w < 8; w++) v += whist[w][tid];
        // warp suffix-inclusive scan (bin order)
        #pragma unroll
        for (int off = 1; off < 32; off <<= 1) {
            unsigned t2 = __shfl_down_sync(0xffffffffu, v, off);
            if (lane + off < 32) v += t2;
        }
        if (lane == 0) warpTot[wid] = v;
        __syncthreads();
        unsigned voff = 0;
        for (int w = wid + 1; w < 8; w++) voff += warpTot[w];
        S[tid] = v + voff;
        __syncthreads();

        unsigned mine = S[tid];
        unsigned nxt = (tid == 255) ? 0u : S[tid + 1];
        if (mine >= rem && nxt < rem) {
            sh_prefix = prefix | ((unsigned)tid << shift);
            sh_rem = rem - nxt;
        }
        __syncthreads();
    }

    unsigned T = sh_prefix;
    int need = (int)sh_rem;

    float se = 0.0f, sed = 0.0f;
    #pragma unroll
    for (int j = 0; j < 8; j++) {
        unsigned uu = ur[j];
        int i = tid * 8 + j;
        if (uu > T) {
            float e = __expf(untr(uu) - vmax);
            se += e;
            sed += e * (float)abs(i - f);
        } else if (uu == T) {
            int p = atomicAdd(&eqCount, 1);
            if (p < 256) eqIdx[p] = i;
        }
    }
    #pragma unroll
    for (int o = 16; o; o >>= 1) {
        se  += __shfl_down_sync(0xffffffffu, se, o);
        sed += __shfl_down_sync(0xffffffffu, sed, o);
    }
    if (lane == 0) { wse[wid] = se; wsed[wid] = sed; }
    __syncthreads();
    if (tid == 0) {
        float SE = 0, SED = 0;
        for (int w = 0; w < 8; w++) { SE += wse[w]; SED += wsed[w]; }
        int ec = eqCount; if (ec > 256) ec = 256;
        float eT = __expf(untr(T) - vmax);
        int take = need < ec ? need : ec;
        if (ec > need) {
            for (int a = 1; a < ec; a++) {
                int key = eqIdx[a]; int bnd = a - 1;
                while (bnd >= 0 && eqIdx[bnd] > key) { eqIdx[bnd+1] = eqIdx[bnd]; bnd--; }
                eqIdx[bnd+1] = key;
            }
        }
        int sumd = 0;
        for (int j = 0; j < take; j++) sumd += abs(eqIdx[j] - f);
        SE  += (float)take * eT;
        SED += eT * (float)sumd;
        g_C[row] = SED / ((float)KTOP * SE);
    }
}

// ---------------------------------------------------------------------------
// Kernel 5: out = mean( exp(-C + min(C) - 1e-6) )
// ---------------------------------------------------------------------------
__global__ void __launch_bounds__(1024) final_kernel(float* __restrict__ out) {
    int tid = threadIdx.x;
    __shared__ float wred[32];
    __shared__ float s_min;

    float mn = 3.4e38f;
    for (int i = tid; i < ROWS; i += 1024) mn = fminf(mn, g_C[i]);
    #pragma unroll
    for (int o = 16; o; o >>= 1) mn = fminf(mn, __shfl_down_sync(0xffffffffu, mn, o));
    if ((tid & 31) == 0) wred[tid >> 5] = mn;
    __syncthreads();
    if (tid == 0) {
        float m2 = wred[0];
        for (int w = 1; w < 32; w++) m2 = fminf(m2, wred[w]);
        s_min = m2;
    }
    __syncthreads();
    float cmin = s_min;

    float s = 0.0f;
    for (int i = tid; i < ROWS; i += 1024) s += expf(-g_C[i] + cmin - 1e-6f);
    #pragma unroll
    for (int o = 16; o; o >>= 1) s += __shfl_down_sync(0xffffffffu, s, o);
    __syncthreads();
    if ((tid & 31) == 0) wred[tid >> 5] = s;
    __syncthreads();
    if (tid == 0) {
        float S = 0;
        for (int w = 0; w < 32; w++) S += wred[w];
        out[0] = S / (float)ROWS;
    }
}

extern "C" void kernel_launch(void* const* d_in, const int* in_sizes, int n_in,
                              void* d_out, int out_size) {
    const float* X  = (const float*)d_in[0];
    const float* Mm = (const float*)d_in[1];
    float* out = (float*)d_out;

    stats_kernel<<<BB, 1024>>>(X, Mm);
    norm_kernel<<<dim3(16, BB), 256>>>(X, Mm);
    gemm_kernel<<<dim3(136, 1, BB), 256>>>();
    topk_kernel<<<ROWS, 256>>>();
    final_kernel<<<1, 1024>>>(out);
}

// round 8
// speedup vs baseline: 2.5715x; 1.9405x over previous
#include <cuda_runtime.h>
#include <math.h>

#define BB 16
#define FF 2048
#define NSP 64
#define ROWS (BB*FF)      // 32768
#define KTOP 1024

// Scratch (device globals; no allocation in kernel_launch)
__device__ float g_A[BB*FF*128];                 // [b][f][0:64]=Xn, [64:128]=Mn  (16 MB)
__device__ float g_YX[67108864];                 // [b][f][g]  (256 MB)
__device__ float g_stats[BB*4*NSP];
__device__ float g_C[ROWS];

// ---------------------------------------------------------------------------
// Kernel 1: per-(b,n) sum and sumsq over F for X and M
// ---------------------------------------------------------------------------
__global__ void __launch_bounds__(1024) stats_kernel(const float* __restrict__ X,
                                                     const float* __restrict__ Mm) {
    int b = blockIdx.x;
    int tid = threadIdx.x;
    int n4 = tid & 15;
    int chunk = tid >> 4;

    const float4* X4 = (const float4*)X + (size_t)b * FF * 16;
    const float4* M4 = (const float4*)Mm + (size_t)b * FF * 16;

    float4 sx = {0,0,0,0}, sxx = {0,0,0,0}, sm = {0,0,0,0}, smm = {0,0,0,0};
    int f0 = chunk * 32;
    for (int r = 0; r < 32; r++) {
        float4 xv = X4[(size_t)(f0 + r) * 16 + n4];
        sx.x += xv.x; sx.y += xv.y; sx.z += xv.z; sx.w += xv.w;
        sxx.x += xv.x*xv.x; sxx.y += xv.y*xv.y; sxx.z += xv.z*xv.z; sxx.w += xv.w*xv.w;
        float4 mv = M4[(size_t)(f0 + r) * 16 + n4];
        sm.x += mv.x; sm.y += mv.y; sm.z += mv.z; sm.w += mv.w;
        smm.x += mv.x*mv.x; smm.y += mv.y*mv.y; smm.z += mv.z*mv.z; smm.w += mv.w*mv.w;
    }

    __shared__ float4 red[64][16];
    __shared__ float sum1[64], sum2[64], sum3[64], sum4[64];

    red[chunk][n4] = sx; __syncthreads();
    if (tid < 64) {
        float s = 0;
        for (int c = 0; c < 64; c++) {
            float4 q = red[c][tid >> 2];
            float v = (tid & 2) ? ((tid & 1) ? q.w : q.z) : ((tid & 1) ? q.y : q.x);
            s += v;
        }
        sum1[tid] = s;
    }
    __syncthreads();
    red[chunk][n4] = sxx; __syncthreads();
    if (tid < 64) {
        float s = 0;
        for (int c = 0; c < 64; c++) {
            float4 q = red[c][tid >> 2];
            float v = (tid & 2) ? ((tid & 1) ? q.w : q.z) : ((tid & 1) ? q.y : q.x);
            s += v;
        }
        sum2[tid] = s;
    }
    __syncthreads();
    red[chunk][n4] = sm; __syncthreads();
    if (tid < 64) {
        float s = 0;
        for (int c = 0; c < 64; c++) {
            float4 q = red[c][tid >> 2];
            float v = (tid & 2) ? ((tid & 1) ? q.w : q.z) : ((tid & 1) ? q.y : q.x);
            s += v;
        }
        sum3[tid] = s;
    }
    __syncthreads();
    red[chunk][n4] = smm; __syncthreads();
    if (tid < 64) {
        float s = 0;
        for (int c = 0; c < 64; c++) {
            float4 q = red[c][tid >> 2];
            float v = (tid & 2) ? ((tid & 1) ? q.w : q.z) : ((tid & 1) ? q.y : q.x);
            s += v;
        }
        sum4[tid] = s;

        float meanX = sum1[tid] * (1.0f / FF);
        float invX  = 1.0f / (sqrtf(fmaxf(sum2[tid] - (float)FF * meanX * meanX, 0.0f)) + 1e-10f);
        float meanM = sum3[tid] * (1.0f / FF);
        float invM  = 1.0f / (sqrtf(fmaxf(sum4[tid] - (float)FF * meanM * meanM, 0.0f)) + 1e-10f);
        g_stats[b*256 + tid]       = meanX;
        g_stats[b*256 + 64 + tid]  = invX;
        g_stats[b*256 + 128 + tid] = meanM;
        g_stats[b*256 + 192 + tid] = invM;
    }
}

// ---------------------------------------------------------------------------
// Kernel 2: write A[b][f][c] = normalized [Xn | Mn]
// ---------------------------------------------------------------------------
__global__ void __launch_bounds__(256) norm_kernel(const float* __restrict__ X,
                                                   const float* __restrict__ Mm) {
    int b = blockIdx.y;
    int fbase = blockIdx.x * 128;
    int tid = threadIdx.x;

    __shared__ float s_mean[128], s_inv[128];
    if (tid < 64) {
        s_mean[tid] = g_stats[b*256 + tid];
        s_inv[tid]  = g_stats[b*256 + 64 + tid];
    } else if (tid < 128) {
        s_mean[tid] = g_stats[b*256 + 64 + tid];
        s_inv[tid]  = g_stats[b*256 + 128 + tid];
    }
    __syncthreads();

    int c = tid & 127;
    int rh = tid >> 7;
    const float* src = (c < 64) ? (X + (size_t)b * FF * 64 + c)
                                : (Mm + (size_t)b * FF * 64 + (c - 64));
    float mean = s_mean[c], inv = s_inv[c];
    for (int r = 0; r < 64; r++) {
        int f = fbase + r * 2 + rh;
        float v = src[(size_t)f * 64];
        g_A[((size_t)b * FF + f) * 128 + c] = (v - mean) * inv;
    }
}

// ---------------------------------------------------------------------------
// Kernel 3: symmetric GEMM. YX = A @ B^T (B cols = A cols rotated by 64).
// Only upper-triangular tiles computed; off-diagonal tiles written twice
// (direct + transposed). Inner loop uses packed fma.rn.f32x2.
// ---------------------------------------------------------------------------
#define FFMA2(d, a, bb) asm("fma.rn.f32x2 %0, %1, %2, %0;" : "+l"(d) : "l"(a), "l"(bb))

__device__ __forceinline__ unsigned long long packdup(float x) {
    unsigned long long d;
    asm("mov.b64 %0, {%1, %1};" : "=l"(d) : "f"(x));
    return d;
}
__device__ __forceinline__ float2 unpk(unsigned long long d) {
    float2 r; asm("mov.b64 {%0, %1}, %2;" : "=f"(r.x), "=f"(r.y) : "l"(d));
    return r;
}

__global__ void __launch_bounds__(256, 2) gemm_kernel() {
    int b = blockIdx.z;
    int t = blockIdx.x;            // 0..135 triangular index
    int rr = 0;
    while (t >= 16 - rr) { t -= 16 - rr; rr++; }
    const int mt = rr * 128;
    const int nt = (rr + t) * 128;

    int tid = threadIdx.x;
    int tx = tid & 15, ty = tid >> 4;

    __shared__ __align__(16) float As[32][132];
    __shared__ __align__(16) float Bs[32][132];

    const float* Abase = g_A + ((size_t)b * FF + mt) * 128;
    const float* Bbase = g_A + ((size_t)b * FF + nt) * 128;

    unsigned long long acc2[8][4];
    #pragma unroll
    for (int i = 0; i < 8; i++)
        #pragma unroll
        for (int j = 0; j < 4; j++) acc2[i][j] = 0ULL;

    const int lrow = tid >> 3;            // 0..31
    const int kg = (tid & 7) * 4;         // 0,4,...,28
    const int vkg = ((kg >> 2) & 7) << 2; // store-side swizzle

    for (int kc = 0; kc < 4; kc++) {
        int aoff = kc * 32;
        int boff = (aoff + 64) & 127;
        #pragma unroll
        for (int l = 0; l < 4; l++) {
            int rowi = lrow + l * 32;
            float4 va = *(const float4*)(Abase + (size_t)rowi * 128 + aoff + kg);
            float4 vb = *(const float4*)(Bbase + (size_t)rowi * 128 + boff + kg);
            int pr = rowi ^ vkg;
            As[kg+0][pr] = va.x; As[kg+1][pr] = va.y;
            As[kg+2][pr] = va.z; As[kg+3][pr] = va.w;
            Bs[kg+0][pr] = vb.x; Bs[kg+1][pr] = vb.y;
            Bs[kg+2][pr] = vb.z; Bs[kg+3][pr] = vb.w;
        }
        __syncthreads();
        #pragma unroll
        for (int kk = 0; kk < 32; kk++) {
            int vv = ((kk >> 2) & 7) << 2;
            const float4 a0 = *(const float4*)&As[kk][(ty*8) ^ vv];
            const float4 a1 = *(const float4*)&As[kk][(ty*8+4) ^ vv];
            const ulonglong2 b0 = *(const ulonglong2*)&Bs[kk][(tx*4) ^ vv];
            const ulonglong2 b1 = *(const ulonglong2*)&Bs[kk][(64+tx*4) ^ vv];
            float av[8] = {a0.x,a0.y,a0.z,a0.w,a1.x,a1.y,a1.z,a1.w};
            #pragma unroll
            for (int i = 0; i < 8; i++) {
                unsigned long long aa = packdup(av[i]);
                FFMA2(acc2[i][0], aa, b0.x);
                FFMA2(acc2[i][1], aa, b0.y);
                FFMA2(acc2[i][2], aa, b1.x);
                FFMA2(acc2[i][3], aa, b1.y);
            }
        }
        __syncthreads();
    }

    float vals[8][8];
    #pragma unroll
    for (int i = 0; i < 8; i++)
        #pragma unroll
        for (int j = 0; j < 4; j++) {
            float2 p = unpk(acc2[i][j]);
            vals[i][j*2]   = p.x;
            vals[i][j*2+1] = p.y;
        }

    // direct write: rows mt+ty*8+i, cols nt+tx*4 (+64)
    {
        float* outp = g_YX + ((size_t)b * FF + mt + ty*8) * FF + nt + tx*4;
        #pragma unroll
        for (int i = 0; i < 8; i++) {
            float4 w0 = {vals[i][0], vals[i][1], vals[i][2], vals[i][3]};
            float4 w1 = {vals[i][4], vals[i][5], vals[i][6], vals[i][7]};
            *(float4*)(outp + (size_t)i * FF)      = w0;
            *(float4*)(outp + (size_t)i * FF + 64) = w1;
        }
    }

    // transposed write for off-diagonal tiles: rows nt+col, cols mt+ty*8..
    if (mt != nt) {
        float* outt = g_YX + ((size_t)b * FF + nt) * FF + mt + ty*8;
        #pragma unroll
        for (int j = 0; j < 8; j++) {
            int col = (j < 4) ? (tx*4 + j) : (64 + tx*4 + (j - 4));
            float4 lo = {vals[0][j], vals[1][j], vals[2][j], vals[3][j]};
            float4 hi = {vals[4][j], vals[5][j], vals[6][j], vals[7][j]};
            *(float4*)(outt + (size_t)col * FF)     = lo;
            *(float4*)(outt + (size_t)col * FF + 4) = hi;
        }
    }
}

// ---------------------------------------------------------------------------
// Kernel 4: per-row top-1024 threshold via single 11-bit histogram pass +
// candidate compaction + exact rank; then exp sums -> C[row].
// Fallback passes (bits 10-20, 0-9) only if threshold bucket > 1024 elems.
// ---------------------------------------------------------------------------
__device__ __forceinline__ float untr(unsigned uu) {
    unsigned bts = uu ^ ((uu & 0x80000000u) ? 0x80000000u : 0xFFFFFFFFu);
    return __uint_as_float(bts);
}

__global__ void __launch_bounds__(256) topk_kernel() {
    int row = blockIdx.x;
    int f = row & (FF - 1);
    const float4* yr = (const float4*)(g_YX + (size_t)row * FF);
    int tid = threadIdx.x;
    int lane = tid & 31, wid = tid >> 5;

    __shared__ unsigned hist[2048];          // reused as candidate buffer
    __shared__ unsigned warpTot[8];
    __shared__ unsigned sh_bucket, sh_rem, sh_cnt, sh_T, sh_need;
    __shared__ int candCount;
    __shared__ float wse[8], wsed[8];
    __shared__ int eqCount;
    __shared__ int eqIdx[256];

    if (tid == 0) { eqCount = 0; candCount = 0; sh_rem = KTOP; }

    // load row into registers, monotone uint transform
    float4 v0 = yr[tid*2], v1 = yr[tid*2 + 1];
    float fv[8] = {v0.x,v0.y,v0.z,v0.w,v1.x,v1.y,v1.z,v1.w};
    unsigned ur[8];
    #pragma unroll
    for (int j = 0; j < 8; j++) {
        unsigned bts = __float_as_uint(fv[j]);
        ur[j] = bts ^ ((unsigned)((int)bts >> 31) | 0x80000000u);
    }

    unsigned prefix = 0;
    int lowBit = 32;

    #pragma unroll 1
    for (int pass = 0; pass < 3; pass++) {
        // zero histogram (vectorized)
        uint4 z = {0,0,0,0};
        *(uint4*)&hist[tid*8]     = z;
        *(uint4*)&hist[tid*8 + 4] = z;
        __syncthreads();
        unsigned rem = sh_rem;

        // histogram
        #pragma unroll
        for (int j = 0; j < 8; j++) {
            unsigned uu = ur[j];
            bool m = (pass == 0) || ((uu >> lowBit) == (prefix >> lowBit));
            if (m) {
                unsigned key = (pass == 0) ? (uu >> 21)
                             : (pass == 1) ? ((uu >> 10) & 0x7FFu)
                                           : ((uu & 0x3FFu) << 1);
                atomicAdd(&hist[key], 1u);
            }
        }
        __syncthreads();

        // suffix scan over 2048 bins: thread t owns bins [8t, 8t+8)
        unsigned h[8], ls[8];
        #pragma unroll
        for (int j = 0; j < 8; j++) h[j] = hist[tid*8 + j];
        ls[7] = h[7];
        #pragma unroll
        for (int j = 6; j >= 0; j--) ls[j] = ls[j+1] + h[j];
        unsigned total = ls[0];
        unsigned incl = total;
        #pragma unroll
        for (int off = 1; off < 32; off <<= 1) {
            unsigned t2 = __shfl_down_sync(0xffffffffu, incl, off);
            if (lane + off < 32) incl += t2;
        }
        if (lane == 0) warpTot[wid] = incl;
        __syncthreads();
        unsigned offAbove = incl - total;
        for (int w = wid + 1; w < 8; w++) offAbove += warpTot[w];

        // find crossing bin: S[bin] >= rem > S[bin+1]
        #pragma unroll
        for (int j = 0; j < 8; j++) {
            unsigned Sj  = offAbove + ls[j];
            unsigned Sj1 = offAbove + (j < 7 ? ls[j+1] : 0u);
            if (Sj >= rem && Sj1 < rem) {
                sh_bucket = (unsigned)(tid*8 + j);
                sh_rem    = rem - Sj1;
                sh_cnt    = h[j];
            }
        }
        __syncthreads();

        unsigned bucket = sh_bucket;
        unsigned cnt = sh_cnt;
        if (pass == 0)      { prefix = bucket << 21;        lowBit = 21; }
        else if (pass == 1) { prefix |= bucket << 10;       lowBit = 10; }
        else                { prefix |= (bucket >> 1);      lowBit = 0;  }
        if (cnt <= 1024u || lowBit == 0) break;
    }

    unsigned T;
    int need;
    if (lowBit == 0) {
        T = prefix;
        need = (int)sh_rem;
    } else {
        unsigned rem2 = sh_rem;
        // compact candidates (those sharing the selected prefix) into hist area
        unsigned* cu = hist;
        #pragma unroll
        for (int j = 0; j < 8; j++) {
            unsigned uu = ur[j];
            if ((uu >> lowBit) == (prefix >> lowBit)) {
                int p = atomicAdd(&candCount, 1);
                cu[p] = uu;
            }
        }
        __syncthreads();
        int cnt = candCount;
        // exact rank: T = rem2-th largest candidate (32-bit exact)
        for (int t2 = tid; t2 < cnt; t2 += 256) {
            unsigned v = cu[t2];
            unsigned g = 0, e = 0;
            for (int i = 0; i < cnt; i++) {
                unsigned w = cu[i];
                g += (w > v);
                e += (w == v);
            }
            if (g < rem2 && g + e >= rem2) { sh_T = v; sh_need = rem2 - g; }
        }
        __syncthreads();
        T = sh_T;
        need = (int)sh_need;
    }

    // final pass: sums over elements > T, collect == T
    float se = 0.0f, sed = 0.0f;
    #pragma unroll
    for (int j = 0; j < 8; j++) {
        unsigned uu = ur[j];
        int i = tid * 8 + j;
        if (uu > T) {
            float e = __expf(untr(uu));
            se += e;
            sed += e * (float)abs(i - f);
        } else if (uu == T) {
            int p = atomicAdd(&eqCount, 1);
            if (p < 256) eqIdx[p] = i;
        }
    }
    #pragma unroll
    for (int o = 16; o; o >>= 1) {
        se  += __shfl_down_sync(0xffffffffu, se, o);
        sed += __shfl_down_sync(0xffffffffu, sed, o);
    }
    if (lane == 0) { wse[wid] = se; wsed[wid] = sed; }
    __syncthreads();
    if (tid == 0) {
        float SE = 0, SED = 0;
        for (int w = 0; w < 8; w++) { SE += wse[w]; SED += wsed[w]; }
        int ec = eqCount; if (ec > 256) ec = 256;
        float eT = __expf(untr(T));
        int take = need < ec ? need : ec;
        if (ec > need) {
            // jax tie-break: lower index first among equals
            for (int a = 1; a < ec; a++) {
                int key = eqIdx[a]; int bnd = a - 1;
                while (bnd >= 0 && eqIdx[bnd] > key) { eqIdx[bnd+1] = eqIdx[bnd]; bnd--; }
                eqIdx[bnd+1] = key;
            }
        }
        int sumd = 0;
        for (int j = 0; j < take; j++) sumd += abs(eqIdx[j] - f);
        SE  += (float)take * eT;
        SED += eT * (float)sumd;
        g_C[row] = SED / ((float)KTOP * SE);
    }
}

// ---------------------------------------------------------------------------
// Kernel 5: out = mean( exp(-C + min(C) - 1e-6) )
// ---------------------------------------------------------------------------
__global__ void __launch_bounds__(1024) final_kernel(float* __restrict__ out) {
    int tid = threadIdx.x;
    __shared__ float wred[32];
    __shared__ float s_min;

    float mn = 3.4e38f;
    for (int i = tid; i < ROWS; i += 1024) mn = fminf(mn, g_C[i]);
    #pragma unroll
    for (int o = 16; o; o >>= 1) mn = fminf(mn, __shfl_down_sync(0xffffffffu, mn, o));
    if ((tid & 31) == 0) wred[tid >> 5] = mn;
    __syncthreads();
    if (tid == 0) {
        float m2 = wred[0];
        for (int w = 1; w < 32; w++) m2 = fminf(m2, wred[w]);
        s_min = m2;
    }
    __syncthreads();
    float cmin = s_min;

    float s = 0.0f;
    for (int i = tid; i < ROWS; i += 1024) s += expf(-g_C[i] + cmin - 1e-6f);
    #pragma unroll
    for (int o = 16; o; o >>= 1) s += __shfl_down_sync(0xffffffffu, s, o);
    __syncthreads();
    if ((tid & 31) == 0) wred[tid >> 5] = s;
    __syncthreads();
    if (tid == 0) {
        float S = 0;
        for (int w = 0; w < 32; w++) S += wred[w];
        out[0] = S / (float)ROWS;
    }
}

extern "C" void kernel_launch(void* const* d_in, const int* in_sizes, int n_in,
                              void* d_out, int out_size) {
    const float* X  = (const float*)d_in[0];
    const float* Mm = (const float*)d_in[1];
    float* out = (float*)d_out;

    stats_kernel<<<BB, 1024>>>(X, Mm);
    norm_kernel<<<dim3(16, BB), 256>>>(X, Mm);
    gemm_kernel<<<dim3(136, 1, BB), 256>>>();
    topk_kernel<<<ROWS, 256>>>();
    final_kernel<<<1, 1024>>>(out);
}